// round 5
// baseline (speedup 1.0000x reference)
#include <cuda_runtime.h>

// SpikeLayer LIF scan: x [B=64, T=8, C=256, H=32, W=32] f32 -> spikes, same shape.
// mem = mem*0.25 + x; spike = (mem - 0.5) > 0; mem = (1-spike)*mem.
//
// R5: one thread owns 8 contiguous neurons (2x float4) across all 8 timesteps.
// 16 front-batched independent LDG.128 per thread -> 8KB contiguous per
// warp-timestep, doubling bytes-in-flight per warp vs R4 to amortize DRAM
// read/write turnaround. Recurrence in registers. Flat one-shot 2D grid
// (y = batch), default cache ops, 32-bit indexing.

#define LIF_T 8
#define VTH 0.5f
#define DECAY 0.25f
#define CHW4 65536u                  // C*H*W/4 float4 vectors per (b,t) slice
#define BSTRIDE (CHW4 * 8u)          // float4 vectors per batch sample

__device__ __forceinline__ void lif4(float4* v, float& m0, float& m1,
                                     float& m2, float& m3)
{
    m0 = fmaf(m0, DECAY, v->x);
    m1 = fmaf(m1, DECAY, v->y);
    m2 = fmaf(m2, DECAY, v->z);
    m3 = fmaf(m3, DECAY, v->w);
    float s0 = (m0 > VTH) ? 1.f : 0.f;
    float s1 = (m1 > VTH) ? 1.f : 0.f;
    float s2 = (m2 > VTH) ? 1.f : 0.f;
    float s3 = (m3 > VTH) ? 1.f : 0.f;
    m0 = (s0 != 0.f) ? 0.f : m0;
    m1 = (s1 != 0.f) ? 0.f : m1;
    m2 = (s2 != 0.f) ? 0.f : m2;
    m3 = (s3 != 0.f) ? 0.f : m3;
    v->x = s0; v->y = s1; v->z = s2; v->w = s3;
}

__global__ __launch_bounds__(256) void lif_scan_kernel(
    const float4* __restrict__ x, float4* __restrict__ out)
{
    // Each thread: 2 adjacent float4 vectors (8 neurons), all 8 timesteps.
    unsigned n    = (blockIdx.x * 256u + threadIdx.x) * 2u;   // [0, CHW4), step 2
    unsigned base = blockIdx.y * BSTRIDE + n;

    float4 va[LIF_T], vb[LIF_T];
    // Front-batched independent loads: 16x LDG.128 (8KB/warp per timestep)
    #pragma unroll
    for (int t = 0; t < LIF_T; t++) {
        va[t] = x[base + (unsigned)t * CHW4];
        vb[t] = x[base + (unsigned)t * CHW4 + 1u];
    }

    float a0 = 0.f, a1 = 0.f, a2 = 0.f, a3 = 0.f;
    float b0 = 0.f, b1 = 0.f, b2 = 0.f, b3 = 0.f;
    #pragma unroll
    for (int t = 0; t < LIF_T; t++) {
        lif4(&va[t], a0, a1, a2, a3);
        lif4(&vb[t], b0, b1, b2, b3);
    }

    #pragma unroll
    for (int t = 0; t < LIF_T; t++) {
        out[base + (unsigned)t * CHW4]      = va[t];
        out[base + (unsigned)t * CHW4 + 1u] = vb[t];
    }
}

extern "C" void kernel_launch(void* const* d_in, const int* in_sizes, int n_in,
                              void* d_out, int out_size)
{
    const float4* x = (const float4*)d_in[0];
    float4* out = (float4*)d_out;

    unsigned total   = (unsigned)in_sizes[0];          // B*T*C*H*W
    unsigned batches = total / (LIF_T * CHW4 * 4u);    // = 64 for bench shape

    dim3 grid(CHW4 / (256u * 2u), batches, 1);         // (128, 64) = 8192 CTAs
    lif_scan_kernel<<<grid, 256>>>(x, out);
}

// round 6
// speedup vs baseline: 1.0716x; 1.0716x over previous
#include <cuda_runtime.h>

// SpikeLayer LIF scan: x [B=64, T=8, C=256, H=32, W=32] f32 -> spikes, same shape.
// mem = mem*0.25 + x; spike = (mem - 0.5) > 0; mem = (1-spike)*mem.
//
// R6: one thread owns 8 neurons as TWO BLOCK-STRIDED float4s (n and n+256),
// so all 16 front-batched LDG.128 are fully coalesced 4KB warp accesses
// (fixes R5's stride-2 sector waste) while doubling per-thread MLP to 16.
// Recurrence in registers. Flat 2D grid (y=batch), default cache ops, 32-bit math.

#define LIF_T 8
#define VTH 0.5f
#define DECAY 0.25f
#define CHW4 65536u                  // C*H*W/4 float4 vectors per (b,t) slice
#define BSTRIDE (CHW4 * 8u)          // float4 vectors per batch sample
#define TPB 256u

__device__ __forceinline__ void lif4(float4* v, float& m0, float& m1,
                                     float& m2, float& m3)
{
    m0 = fmaf(m0, DECAY, v->x);
    m1 = fmaf(m1, DECAY, v->y);
    m2 = fmaf(m2, DECAY, v->z);
    m3 = fmaf(m3, DECAY, v->w);
    float s0 = (m0 > VTH) ? 1.f : 0.f;
    float s1 = (m1 > VTH) ? 1.f : 0.f;
    float s2 = (m2 > VTH) ? 1.f : 0.f;
    float s3 = (m3 > VTH) ? 1.f : 0.f;
    m0 = (s0 != 0.f) ? 0.f : m0;
    m1 = (s1 != 0.f) ? 0.f : m1;
    m2 = (s2 != 0.f) ? 0.f : m2;
    m3 = (s3 != 0.f) ? 0.f : m3;
    v->x = s0; v->y = s1; v->z = s2; v->w = s3;
}

__global__ __launch_bounds__(TPB) void lif_scan_kernel(
    const float4* __restrict__ x, float4* __restrict__ out)
{
    // Block covers 512 consecutive float4: thread i owns n and n+TPB.
    unsigned n    = blockIdx.x * (TPB * 2u) + threadIdx.x;
    unsigned base = blockIdx.y * BSTRIDE + n;

    float4 va[LIF_T], vb[LIF_T];
    // 16 front-batched independent, fully-coalesced LDG.128
    #pragma unroll
    for (int t = 0; t < LIF_T; t++) {
        va[t] = x[base + (unsigned)t * CHW4];
        vb[t] = x[base + (unsigned)t * CHW4 + TPB];
    }

    float a0 = 0.f, a1 = 0.f, a2 = 0.f, a3 = 0.f;
    float b0 = 0.f, b1 = 0.f, b2 = 0.f, b3 = 0.f;
    #pragma unroll
    for (int t = 0; t < LIF_T; t++) {
        lif4(&va[t], a0, a1, a2, a3);
        lif4(&vb[t], b0, b1, b2, b3);
    }

    #pragma unroll
    for (int t = 0; t < LIF_T; t++) {
        out[base + (unsigned)t * CHW4]       = va[t];
        out[base + (unsigned)t * CHW4 + TPB] = vb[t];
    }
}

extern "C" void kernel_launch(void* const* d_in, const int* in_sizes, int n_in,
                              void* d_out, int out_size)
{
    const float4* x = (const float4*)d_in[0];
    float4* out = (float4*)d_out;

    unsigned total   = (unsigned)in_sizes[0];          // B*T*C*H*W
    unsigned batches = total / (LIF_T * CHW4 * 4u);    // = 64 for bench shape

    dim3 grid(CHW4 / (TPB * 2u), batches, 1);          // (128, 64) = 8192 CTAs
    lif_scan_kernel<<<grid, TPB>>>(x, out);
}

// round 7
// speedup vs baseline: 1.0746x; 1.0028x over previous
#include <cuda_runtime.h>

// SpikeLayer LIF scan: x [B=64, T=8, C=256, H=32, W=32] f32 -> spikes, same shape.
// mem = mem*0.25 + x; spike = (mem - 0.5) > 0; mem = (1-spike)*mem.
//
// Converged configuration (R4) with the last untested knob: 512-thread CTAs.
// One thread = 4 neurons (one float4) across all 8 timesteps; recurrence in
// registers; front-batched MLP=8 fully-coalesced LDG.128; default cache ops;
// flat 2D grid (y = batch); all 32-bit index math. Kernel is pinned at the
// HBM mixed read/write ceiling (~6.8 TB/s, traffic = 1 GiB floor).

#define LIF_T 8
#define VTH 0.5f
#define DECAY 0.25f
#define CHW4 65536u                  // C*H*W/4 float4 vectors per (b,t) slice
#define BSTRIDE (CHW4 * 8u)          // float4 vectors per batch sample
#define TPB 512u

__global__ __launch_bounds__(TPB) void lif_scan_kernel(
    const float4* __restrict__ x, float4* __restrict__ out)
{
    unsigned n    = blockIdx.x * TPB + threadIdx.x;    // [0, CHW4)
    unsigned base = blockIdx.y * BSTRIDE + n;

    float4 v[LIF_T];
    // Front-batched independent loads: MLP = 8 LDG.128
    #pragma unroll
    for (int t = 0; t < LIF_T; t++)
        v[t] = x[base + (unsigned)t * CHW4];

    float mx = 0.f, my = 0.f, mz = 0.f, mw = 0.f;
    #pragma unroll
    for (int t = 0; t < LIF_T; t++) {
        mx = fmaf(mx, DECAY, v[t].x);
        my = fmaf(my, DECAY, v[t].y);
        mz = fmaf(mz, DECAY, v[t].z);
        mw = fmaf(mw, DECAY, v[t].w);
        float sx = (mx > VTH) ? 1.f : 0.f;
        float sy = (my > VTH) ? 1.f : 0.f;
        float sz = (mz > VTH) ? 1.f : 0.f;
        float sw = (mw > VTH) ? 1.f : 0.f;
        // hard reset where spiked
        mx = (sx != 0.f) ? 0.f : mx;
        my = (sy != 0.f) ? 0.f : my;
        mz = (sz != 0.f) ? 0.f : mz;
        mw = (sw != 0.f) ? 0.f : mw;
        v[t].x = sx; v[t].y = sy; v[t].z = sz; v[t].w = sw;
    }

    #pragma unroll
    for (int t = 0; t < LIF_T; t++)
        out[base + (unsigned)t * CHW4] = v[t];
}

extern "C" void kernel_launch(void* const* d_in, const int* in_sizes, int n_in,
                              void* d_out, int out_size)
{
    const float4* x = (const float4*)d_in[0];
    float4* out = (float4*)d_out;

    unsigned total   = (unsigned)in_sizes[0];          // B*T*C*H*W
    unsigned batches = total / (LIF_T * CHW4 * 4u);    // = 64 for bench shape

    dim3 grid(CHW4 / TPB, batches, 1);                 // (128, 64) = 8192 CTAs
    lif_scan_kernel<<<grid, TPB>>>(x, out);
}